// round 2
// baseline (speedup 1.0000x reference)
#include <cuda_runtime.h>

// FlashSelfAttention: B=2, S=2048, H=16, D=128, fp32, causal + -slope*sqrt(i-j) bias.
// fp32 CUDA-core flash attention, 64x64 tiles, online softmax. Baseline anchor.

namespace {
constexpr int B = 2, S = 2048, H = 16, D = 128;
constexpr int BM = 64, BN = 64;
constexpr int QS = 132;   // padded row stride (floats) for Q/K/V smem tiles (odd # of 16B chunks)
constexpr int PS = 68;    // padded row stride (floats) for P smem tile
constexpr int SMEM_FLOATS = 3 * BM * QS + BM * PS;
constexpr int SMEM_BYTES  = SMEM_FLOATS * (int)sizeof(float);  // 118784 B
}

__global__ __launch_bounds__(256, 1)
void fa_fwd_kernel(const float* __restrict__ gq,
                   const float* __restrict__ gk,
                   const float* __restrict__ gv,
                   float* __restrict__ gout)
{
    extern __shared__ float sm[];
    float* sQ = sm;                 // [BM][QS]
    float* sK = sQ + BM * QS;       // [BN][QS]
    float* sV = sK + BN * QS;       // [BN][QS]
    float* sP = sV + BN * QS;       // [BM][PS]

    const int qt = blockIdx.x;      // query tile
    const int h  = blockIdx.y;
    const int b  = blockIdx.z;

    const int tid = threadIdx.x;
    const int tx = tid & 15;        // 16 col-threads
    const int ty = tid >> 4;        // 16 row-threads

    const float scale = 0.08838834764831845f;            // 1/sqrt(128)
    const float slope = exp2f(-0.5f * (float)(h + 1));   // alibi slope for H=16

    const size_t row_stride = (size_t)H * D;             // floats between consecutive s
    const size_t bh_base    = ((size_t)b * S * H + (size_t)h) * D;

    const int q0 = qt * BM;

    // ---- stage Q tile (once) ----
    for (int idx = tid; idx < BM * (D / 4); idx += 256) {
        const int r  = idx >> 5;           // 32 float4 per row
        const int c4 = (idx & 31) << 2;
        *(float4*)(sQ + r * QS + c4) =
            *(const float4*)(gq + bh_base + (size_t)(q0 + r) * row_stride + c4);
    }

    float m_i[4], l_i[4];
    float o_acc[4][8];
#pragma unroll
    for (int i = 0; i < 4; ++i) {
        m_i[i] = -1e30f; l_i[i] = 0.0f;
#pragma unroll
        for (int j = 0; j < 8; ++j) o_acc[i][j] = 0.0f;
    }

    for (int kt = 0; kt <= qt; ++kt) {
        const int k0 = kt * BN;

        // ---- stage K/V tiles ----
        for (int idx = tid; idx < BN * (D / 4); idx += 256) {
            const int r  = idx >> 5;
            const int c4 = (idx & 31) << 2;
            const size_t goff = bh_base + (size_t)(k0 + r) * row_stride + c4;
            *(float4*)(sK + r * QS + c4) = *(const float4*)(gk + goff);
            *(float4*)(sV + r * QS + c4) = *(const float4*)(gv + goff);
        }
        __syncthreads();

        // ---- S = Q K^T  (4x4 register micro-tile per thread) ----
        float acc[4][4];
#pragma unroll
        for (int i = 0; i < 4; ++i)
#pragma unroll
            for (int j = 0; j < 4; ++j) acc[i][j] = 0.0f;

        const float* qp = sQ + (ty * 4) * QS;
        const float* kp = sK + (tx * 4) * QS;
#pragma unroll 8
        for (int kk = 0; kk < D; kk += 4) {
            float4 a[4], bb[4];
#pragma unroll
            for (int i = 0; i < 4; ++i) a[i]  = *(const float4*)(qp + i * QS + kk);
#pragma unroll
            for (int j = 0; j < 4; ++j) bb[j] = *(const float4*)(kp + j * QS + kk);
#pragma unroll
            for (int i = 0; i < 4; ++i)
#pragma unroll
                for (int j = 0; j < 4; ++j) {
                    acc[i][j] += a[i].x * bb[j].x;
                    acc[i][j] += a[i].y * bb[j].y;
                    acc[i][j] += a[i].z * bb[j].z;
                    acc[i][j] += a[i].w * bb[j].w;
                }
        }

        // ---- bias + online softmax (row reduce across 16 tx lanes) ----
#pragma unroll
        for (int i = 0; i < 4; ++i) {
            const int gi = q0 + ty * 4 + i;
            float srow[4];
#pragma unroll
            for (int j = 0; j < 4; ++j) {
                const int gj = k0 + tx * 4 + j;
                const int dd = gi - gj;
                const float sq = sqrtf(fmaxf((float)dd, 0.0f));
                const float s  = acc[i][j] * scale - slope * sq;
                srow[j] = (dd >= 0) ? s : -1e30f;
            }
            float mx = fmaxf(fmaxf(srow[0], srow[1]), fmaxf(srow[2], srow[3]));
#pragma unroll
            for (int off = 8; off; off >>= 1)
                mx = fmaxf(mx, __shfl_xor_sync(0xffffffffu, mx, off));

            const float mnew = fmaxf(m_i[i], mx);
            const float corr = __expf(m_i[i] - mnew);
            m_i[i] = mnew;

            float rs = 0.0f;
#pragma unroll
            for (int j = 0; j < 4; ++j) {
                srow[j] = __expf(srow[j] - mnew);
                rs += srow[j];
            }
#pragma unroll
            for (int off = 8; off; off >>= 1)
                rs += __shfl_xor_sync(0xffffffffu, rs, off);

            l_i[i] = l_i[i] * corr + rs;
#pragma unroll
            for (int j = 0; j < 8; ++j) o_acc[i][j] *= corr;

            *(float4*)(sP + (ty * 4 + i) * PS + tx * 4) =
                make_float4(srow[0], srow[1], srow[2], srow[3]);
        }
        __syncthreads();

        // ---- O += P V  (4 rows x (4+4) cols; col halves at +0 and +64) ----
        const float* pp = sP + (ty * 4) * PS;
        const float* vp = sV + tx * 4;
#pragma unroll 8
        for (int kk = 0; kk < BN; ++kk) {
            const float4 v0 = *(const float4*)(vp + kk * QS);
            const float4 v1 = *(const float4*)(vp + kk * QS + 64);
            float pr[4];
#pragma unroll
            for (int i = 0; i < 4; ++i) pr[i] = pp[i * PS + kk];
#pragma unroll
            for (int i = 0; i < 4; ++i) {
                o_acc[i][0] += pr[i] * v0.x;
                o_acc[i][1] += pr[i] * v0.y;
                o_acc[i][2] += pr[i] * v0.z;
                o_acc[i][3] += pr[i] * v0.w;
                o_acc[i][4] += pr[i] * v1.x;
                o_acc[i][5] += pr[i] * v1.y;
                o_acc[i][6] += pr[i] * v1.z;
                o_acc[i][7] += pr[i] * v1.w;
            }
        }
        __syncthreads();
    }

    // ---- epilogue: O /= l, write [b, s, h, d] ----
#pragma unroll
    for (int i = 0; i < 4; ++i) {
        const float inv = 1.0f / l_i[i];
        float* op = gout + bh_base + (size_t)(q0 + ty * 4 + i) * row_stride;
        *(float4*)(op + tx * 4) =
            make_float4(o_acc[i][0] * inv, o_acc[i][1] * inv,
                        o_acc[i][2] * inv, o_acc[i][3] * inv);
        *(float4*)(op + 64 + tx * 4) =
            make_float4(o_acc[i][4] * inv, o_acc[i][5] * inv,
                        o_acc[i][6] * inv, o_acc[i][7] * inv);
    }
}

extern "C" void kernel_launch(void* const* d_in, const int* in_sizes, int n_in,
                              void* d_out, int out_size)
{
    (void)in_sizes; (void)n_in; (void)out_size;
    const float* q = (const float*)d_in[0];
    const float* k = (const float*)d_in[1];
    const float* v = (const float*)d_in[2];
    float* out = (float*)d_out;

    cudaFuncSetAttribute(fa_fwd_kernel,
                         cudaFuncAttributeMaxDynamicSharedMemorySize, SMEM_BYTES);

    dim3 grid(S / BM, H, B);   // (32, 16, 2)
    fa_fwd_kernel<<<grid, 256, SMEM_BYTES>>>(q, k, v, out);
}

// round 5
// speedup vs baseline: 3.2959x; 3.2959x over previous
#include <cuda_runtime.h>
#include <cuda_bf16.h>
#include <cstdint>

// FlashSelfAttention B=2,S=2048,H=16,D=128 fp32, causal + -slope*sqrt(i-j) bias.
// Warp-level mma.sync (bf16 hi/lo compensated, 3-pass) flash attention.
// Base sm_100 ISA only (no tcgen05 -- harness compiles for sm_100, not sm_100a).

#define DEVINL __device__ __forceinline__

namespace {
constexpr int HH = 16, SEQ = 2048, BB = 2;
constexpr int BM = 128, BN = 64, D = 128;
constexpr int NQT = SEQ / BM;            // 16
constexpr int ROWSTR = HH * D;           // 2048 floats between seq positions

constexpr int QSTR = 136;                // padded bf16 row stride (272B = 17 x 16B)
// smem byte offsets
constexpr int OFF_QHI = 0;
constexpr int OFF_QLO = OFF_QHI + BM * QSTR * 2;       // 34816
constexpr int OFF_KHI = OFF_QLO + BM * QSTR * 2;       // 69632
constexpr int OFF_KLO = OFF_KHI + BN * QSTR * 2;       // 87040
constexpr int OFF_VHI = OFF_KLO + BN * QSTR * 2;       // 104448
constexpr int OFF_VLO = OFF_VHI + BN * QSTR * 2;       // 121856
constexpr int OFF_TBL = OFF_VLO + BN * QSTR * 2;       // 139264
constexpr int SMEM_TOTAL = OFF_TBL + SEQ * 4;          // 147456 B

constexpr float LOG2E = 1.4426950408889634f;
}

DEVINL uint32_t smem_u32(const void* p) {
    uint32_t a;
    asm("{ .reg .u64 t; cvta.to.shared.u64 t, %1; cvt.u32.u64 %0, t; }" : "=r"(a) : "l"(p));
    return a;
}
DEVINL float ex2(float x) { float r; asm("ex2.approx.f32 %0, %1;" : "=f"(r) : "f"(x)); return r; }

DEVINL void ldsm4(uint32_t& r0, uint32_t& r1, uint32_t& r2, uint32_t& r3, uint32_t a) {
    asm volatile("ldmatrix.sync.aligned.m8n8.x4.shared.b16 {%0,%1,%2,%3}, [%4];"
                 : "=r"(r0), "=r"(r1), "=r"(r2), "=r"(r3) : "r"(a));
}
DEVINL void ldsm4t(uint32_t& r0, uint32_t& r1, uint32_t& r2, uint32_t& r3, uint32_t a) {
    asm volatile("ldmatrix.sync.aligned.m8n8.x4.trans.shared.b16 {%0,%1,%2,%3}, [%4];"
                 : "=r"(r0), "=r"(r1), "=r"(r2), "=r"(r3) : "r"(a));
}
DEVINL void mma16816(float* c, const uint32_t* a, uint32_t b0, uint32_t b1) {
    asm volatile("mma.sync.aligned.m16n8k16.row.col.f32.bf16.bf16.f32 "
                 "{%0,%1,%2,%3}, {%4,%5,%6,%7}, {%8,%9}, {%0,%1,%2,%3};"
                 : "+f"(c[0]), "+f"(c[1]), "+f"(c[2]), "+f"(c[3])
                 : "r"(a[0]), "r"(a[1]), "r"(a[2]), "r"(a[3]), "r"(b0), "r"(b1));
}

// split 2 floats into packed bf16 hi and residual-lo words
DEVINL void split2(float a, float b, uint32_t& hi, uint32_t& lo) {
    __nv_bfloat16 ha = __float2bfloat16(a), hb = __float2bfloat16(b);
    float ra = a - __bfloat162float(ha), rb = b - __bfloat162float(hb);
    __nv_bfloat16 la = __float2bfloat16(ra), lb = __float2bfloat16(rb);
    hi = (uint32_t)__bfloat16_as_ushort(ha) | ((uint32_t)__bfloat16_as_ushort(hb) << 16);
    lo = (uint32_t)__bfloat16_as_ushort(la) | ((uint32_t)__bfloat16_as_ushort(lb) << 16);
}

__global__ __launch_bounds__(256, 1)
void fa_mma_kernel(const float* __restrict__ gq,
                   const float* __restrict__ gk,
                   const float* __restrict__ gv,
                   float* __restrict__ gout)
{
    extern __shared__ char smc[];
    const uint32_t smb = smem_u32(smc);
    const int tid  = threadIdx.x;
    const int lane = tid & 31;
    const int w    = tid >> 5;          // 8 warps
    const int w16  = w << 4;            // warp's first query row within tile
    const int qr   = lane >> 2;         // row-in-group 0..7
    const int qc   = lane & 3;          // col quad 0..3

    const int qi = blockIdx.x, h = blockIdx.y, b = blockIdx.z;
    const int q0 = qi * BM;
    const size_t bh = ((size_t)b * SEQ * HH + (size_t)h) * D;

    const float scale2 = 0.08838834764831845f * LOG2E;
    const float slope2 = exp2f(-0.5f * (float)(h + 1)) * LOG2E;

    float* tbl = (float*)(smc + OFF_TBL);
    for (int i = tid; i < SEQ; i += 256) tbl[i] = sqrtf((float)i);

    // ---- stage Q (once): 128 rows x 128 f32 -> bf16 hi/lo, row stride 136 ----
    {
        const int r = tid >> 1, half = tid & 1;
        const float4* qg = (const float4*)(gq + bh + (size_t)(q0 + r) * ROWSTR + half * 64);
        char* dhi = smc + OFF_QHI + (r * QSTR + half * 64) * 2;
        char* dlo = smc + OFF_QLO + (r * QSTR + half * 64) * 2;
#pragma unroll
        for (int i = 0; i < 16; ++i) {
            float4 v = qg[i];
            uint32_t h0, l0, h1, l1;
            split2(v.x, v.y, h0, l0);
            split2(v.z, v.w, h1, l1);
            *(uint2*)(dhi + i * 8) = make_uint2(h0, h1);
            *(uint2*)(dlo + i * 8) = make_uint2(l0, l1);
        }
    }

    // ldmatrix per-lane base addresses
    // A (Q): tiles [rows 0-7 | rows 8-15 | rows 0-7,k+8 | rows 8-15,k+8]
    const int rowA = w16 + (lane & 7) + ((lane >> 3) & 1) * 8;
    const int colA = ((lane >> 4) & 1) * 8;
    const uint32_t aQhi = smb + OFF_QHI + (uint32_t)(rowA * QSTR + colA) * 2;
    const uint32_t aQlo = smb + OFF_QLO + (uint32_t)(rowA * QSTR + colA) * 2;
    // B (K): tiles [b0 nt_e | b1 nt_e | b0 nt_o | b1 nt_o]; keys = rows, d = cols
    const int keyB = (lane & 7) + ((lane >> 4) & 1) * 8;
    const int colB = ((lane >> 3) & 1) * 8;
    const uint32_t aKhi = smb + OFF_KHI + (uint32_t)(keyB * QSTR + colB) * 2;
    const uint32_t aKlo = smb + OFF_KLO + (uint32_t)(keyB * QSTR + colB) * 2;
    // B (V, trans): keys = rows (+8 for b1), d = cols (+8 for nt_odd)
    const int keyV = (lane & 7) + ((lane >> 3) & 1) * 8;
    const int colV = ((lane >> 4) & 1) * 8;
    const uint32_t aVhi = smb + OFF_VHI + (uint32_t)(keyV * QSTR + colV) * 2;
    const uint32_t aVlo = smb + OFF_VLO + (uint32_t)(keyV * QSTR + colV) * 2;

    float oacc[16][4];
#pragma unroll
    for (int i = 0; i < 16; ++i)
#pragma unroll
        for (int j = 0; j < 4; ++j) oacc[i][j] = 0.0f;
    float m0 = -1e30f, m1 = -1e30f, l0 = 0.0f, l1 = 0.0f;

    const int nkt = 2 * qi + 2;

    for (int kt = 0; kt < nkt; ++kt) {
        const int k0 = kt * BN;

        // ---- stage K and V tiles: 64 rows x 128 f32 each ----
        __syncthreads();   // previous iter's ldmatrix reads complete
        {
            const int r = tid >> 2, quad = tid & 3;
            const size_t goff = bh + (size_t)(k0 + r) * ROWSTR + quad * 32;
            const float4* kg = (const float4*)(gk + goff);
            const float4* vg = (const float4*)(gv + goff);
            const int so = (r * QSTR + quad * 32) * 2;
#pragma unroll
            for (int i = 0; i < 8; ++i) {
                float4 v = kg[i];
                uint32_t h0, lo0, h1, lo1;
                split2(v.x, v.y, h0, lo0);
                split2(v.z, v.w, h1, lo1);
                *(uint2*)(smc + OFF_KHI + so + i * 8) = make_uint2(h0, h1);
                *(uint2*)(smc + OFF_KLO + so + i * 8) = make_uint2(lo0, lo1);
                float4 u = vg[i];
                split2(u.x, u.y, h0, lo0);
                split2(u.z, u.w, h1, lo1);
                *(uint2*)(smc + OFF_VHI + so + i * 8) = make_uint2(h0, h1);
                *(uint2*)(smc + OFF_VLO + so + i * 8) = make_uint2(lo0, lo1);
            }
        }
        __syncthreads();

        // warp fully masked for this tile? (k0 multiple of 64 >= warp's last row+1)
        const bool active = (q0 + w16 + 15) >= k0;
        if (active) {
            // ---- S = Q K^T : 8 k-steps x 8 n-tiles x 3 passes ----
            float sacc[8][4];
#pragma unroll
            for (int i = 0; i < 8; ++i)
#pragma unroll
                for (int j = 0; j < 4; ++j) sacc[i][j] = 0.0f;

#pragma unroll
            for (int ks = 0; ks < 8; ++ks) {
                uint32_t ah[4], al[4];
                ldsm4(ah[0], ah[1], ah[2], ah[3], aQhi + ks * 32);
                ldsm4(al[0], al[1], al[2], al[3], aQlo + ks * 32);
#pragma unroll
                for (int np = 0; np < 4; ++np) {
                    uint32_t bh0, bh1, bh2, bh3, bl0, bl1, bl2, bl3;
                    const uint32_t off = (uint32_t)(np * 16 * QSTR * 2 + ks * 32);
                    ldsm4(bh0, bh1, bh2, bh3, aKhi + off);
                    ldsm4(bl0, bl1, bl2, bl3, aKlo + off);
                    mma16816(sacc[2 * np],     ah, bh0, bh1);
                    mma16816(sacc[2 * np],     ah, bl0, bl1);
                    mma16816(sacc[2 * np],     al, bh0, bh1);
                    mma16816(sacc[2 * np + 1], ah, bh2, bh3);
                    mma16816(sacc[2 * np + 1], ah, bl2, bl3);
                    mma16816(sacc[2 * np + 1], al, bh2, bh3);
                }
            }

            // ---- softmax over 64 cols; thread owns rows (gi0, gi1), 16 cols each ----
            const int gi0 = q0 + w16 + qr, gi1 = gi0 + 8;
            float sc0[16], sc1[16];
            float rm0 = -1e30f, rm1 = -1e30f;
#pragma unroll
            for (int nt = 0; nt < 8; ++nt) {
                const int cj = k0 + nt * 8 + 2 * qc;
#pragma unroll
                for (int jj = 0; jj < 2; ++jj) {
                    const int d0 = gi0 - (cj + jj);
                    float s = (d0 >= 0) ? sacc[nt][jj] * scale2 - slope2 * tbl[d0] : -1e30f;
                    sc0[nt * 2 + jj] = s;
                    rm0 = fmaxf(rm0, s);
                    const int d1 = gi1 - (cj + jj);
                    float t = (d1 >= 0) ? sacc[nt][2 + jj] * scale2 - slope2 * tbl[d1] : -1e30f;
                    sc1[nt * 2 + jj] = t;
                    rm1 = fmaxf(rm1, t);
                }
            }
            rm0 = fmaxf(rm0, __shfl_xor_sync(0xffffffffu, rm0, 1));
            rm0 = fmaxf(rm0, __shfl_xor_sync(0xffffffffu, rm0, 2));
            rm1 = fmaxf(rm1, __shfl_xor_sync(0xffffffffu, rm1, 1));
            rm1 = fmaxf(rm1, __shfl_xor_sync(0xffffffffu, rm1, 2));

            const float mn0 = fmaxf(m0, rm0), mn1 = fmaxf(m1, rm1);
            const float cr0 = ex2(m0 - mn0),  cr1 = ex2(m1 - mn1);
            m0 = mn0; m1 = mn1;

            float rs0 = 0.0f, rs1 = 0.0f;
#pragma unroll
            for (int j = 0; j < 16; ++j) {
                float p = ex2(sc0[j] - mn0); sc0[j] = p; rs0 += p;
                float q = ex2(sc1[j] - mn1); sc1[j] = q; rs1 += q;
            }
            rs0 += __shfl_xor_sync(0xffffffffu, rs0, 1);
            rs0 += __shfl_xor_sync(0xffffffffu, rs0, 2);
            rs1 += __shfl_xor_sync(0xffffffffu, rs1, 1);
            rs1 += __shfl_xor_sync(0xffffffffu, rs1, 2);
            l0 = l0 * cr0 + rs0;
            l1 = l1 * cr1 + rs1;

            // rescale O
#pragma unroll
            for (int nt = 0; nt < 16; ++nt) {
                oacc[nt][0] *= cr0; oacc[nt][1] *= cr0;
                oacc[nt][2] *= cr1; oacc[nt][3] *= cr1;
            }

            // ---- pack P into A-fragments (hi/lo) ----
            uint32_t phi[4][4], plo[4][4];
#pragma unroll
            for (int ks = 0; ks < 4; ++ks) {
                split2(sc0[4 * ks],     sc0[4 * ks + 1], phi[ks][0], plo[ks][0]);
                split2(sc1[4 * ks],     sc1[4 * ks + 1], phi[ks][1], plo[ks][1]);
                split2(sc0[4 * ks + 2], sc0[4 * ks + 3], phi[ks][2], plo[ks][2]);
                split2(sc1[4 * ks + 2], sc1[4 * ks + 3], phi[ks][3], plo[ks][3]);
            }

            // ---- O += P V : 4 k-steps x 16 n-tiles x 3 passes ----
#pragma unroll
            for (int ks = 0; ks < 4; ++ks) {
#pragma unroll
                for (int np = 0; np < 8; ++np) {
                    uint32_t bh0, bh1, bh2, bh3, bl0, bl1, bl2, bl3;
                    const uint32_t off = (uint32_t)(ks * 16 * QSTR * 2 + np * 32);
                    ldsm4t(bh0, bh1, bh2, bh3, aVhi + off);
                    ldsm4t(bl0, bl1, bl2, bl3, aVlo + off);
                    mma16816(oacc[2 * np],     phi[ks], bh0, bh1);
                    mma16816(oacc[2 * np],     phi[ks], bl0, bl1);
                    mma16816(oacc[2 * np],     plo[ks], bh0, bh1);
                    mma16816(oacc[2 * np + 1], phi[ks], bh2, bh3);
                    mma16816(oacc[2 * np + 1], phi[ks], bl2, bl3);
                    mma16816(oacc[2 * np + 1], plo[ks], bh2, bh3);
                }
            }
        }
    }

    // ---- epilogue: O /= l, stage in smem (reuse Q area), coalesced store ----
    __syncthreads();
    float* stg = (float*)(smc + OFF_QHI);   // [128][132]
    {
        const float inv0 = 1.0f / l0, inv1 = 1.0f / l1;
        float* s0 = stg + (w16 + qr) * 132 + 2 * qc;
        float* s1 = stg + (w16 + qr + 8) * 132 + 2 * qc;
#pragma unroll
        for (int nt = 0; nt < 16; ++nt) {
            *(float2*)(s0 + nt * 8) = make_float2(oacc[nt][0] * inv0, oacc[nt][1] * inv0);
            *(float2*)(s1 + nt * 8) = make_float2(oacc[nt][2] * inv1, oacc[nt][3] * inv1);
        }
    }
    __syncthreads();
    {
        const int col = tid & 127, rh = tid >> 7;
#pragma unroll 4
        for (int it = 0; it < 64; ++it) {
            const int row = it * 2 + rh;
            gout[bh + (size_t)(q0 + row) * ROWSTR + col] = stg[row * 132 + col];
        }
    }
}

extern "C" void kernel_launch(void* const* d_in, const int* in_sizes, int n_in,
                              void* d_out, int out_size)
{
    (void)in_sizes; (void)n_in; (void)out_size;
    const float* q = (const float*)d_in[0];
    const float* k = (const float*)d_in[1];
    const float* v = (const float*)d_in[2];
    float* out = (float*)d_out;

    cudaFuncSetAttribute(fa_mma_kernel,
                         cudaFuncAttributeMaxDynamicSharedMemorySize, SMEM_TOTAL);

    dim3 grid(NQT, HH, BB);   // (16, 16, 2)
    fa_mma_kernel<<<grid, 256, SMEM_TOTAL>>>(q, k, v, out);
}